// round 5
// baseline (speedup 1.0000x reference)
#include <cuda_runtime.h>

// Problem shape (fixed by the benchmark's setup_inputs)
#define BB 16
#define PP 2048
#define QQ 2048

// Single-wave grid: 444 blocks = 3 blocks/SM x 148 SMs, 512 threads each.
//  blocks [0,256):   syn tile + 1 stream chunk
//  blocks [256,272): trace + 1 stream chunk
//  blocks [272,444): stream only (first 68 do 2 chunks, rest 1)
// Stream: 16 MB = 1M float4 = 512 chunks x (512 thr x 4 float4).
#define N_BLK 444
#define NCHUNK 512

// ---------------------------------------------------------------------------
// ONE fused kernel. weight_changes are identically ZERO: every active STDP
// pair has t_pre == t_post == current_time, so dts == 0 and neither the LTP
// (dts>0) nor LTD (dts<0) condition can fire. Hence:
//   weight_changes = 0, new_weights = clip(weights, 0, 1).
// last_pre_spike / last_post_spike / current_time are dead inputs.
// ---------------------------------------------------------------------------
__device__ __forceinline__ void stream_chunk(int c, int tid,
                                             const float4* __restrict__ w4,
                                             float4* __restrict__ wc4,
                                             float4* __restrict__ nw4) {
    const int i0 = c * 2048 + tid;
    const int i1 = i0 + 512;
    const int i2 = i0 + 1024;
    const int i3 = i0 + 1536;
    // MLP=4 front-batched loads
    float4 v0 = w4[i0];
    float4 v1 = w4[i1];
    float4 v2 = w4[i2];
    float4 v3 = w4[i3];
    const float4 zero = make_float4(0.0f, 0.0f, 0.0f, 0.0f);
    wc4[i0] = zero; wc4[i1] = zero; wc4[i2] = zero; wc4[i3] = zero;
    float4 c0, c1, c2, c3;
    c0.x = __saturatef(v0.x); c0.y = __saturatef(v0.y);
    c0.z = __saturatef(v0.z); c0.w = __saturatef(v0.w);
    c1.x = __saturatef(v1.x); c1.y = __saturatef(v1.y);
    c1.z = __saturatef(v1.z); c1.w = __saturatef(v1.w);
    c2.x = __saturatef(v2.x); c2.y = __saturatef(v2.y);
    c2.z = __saturatef(v2.z); c2.w = __saturatef(v2.w);
    c3.x = __saturatef(v3.x); c3.y = __saturatef(v3.y);
    c3.z = __saturatef(v3.z); c3.w = __saturatef(v3.w);
    nw4[i0] = c0; nw4[i1] = c1; nw4[i2] = c2; nw4[i3] = c3;
}

__global__ void __launch_bounds__(512, 3)
k_fused(const float* __restrict__ pre_s,
        const float* __restrict__ post_s,
        const float* __restrict__ w,
        const float* __restrict__ pre_tr,
        const float* __restrict__ post_tr,
        const float* __restrict__ dt_ptr,
        float* __restrict__ o_syn,
        float* __restrict__ o_wc,
        float* __restrict__ o_ptr,
        float* __restrict__ o_qtr,
        float* __restrict__ o_nw) {
    const int bid = blockIdx.x;
    const int tid = threadIdx.x;          // 0..511
    const float4* w4  = (const float4*)w;
    float4*       wc4 = (float4*)o_wc;
    float4*       nw4 = (float4*)o_nw;

    if (bid < 256) {
        // ---- Role B: synaptic_current[b][q] = sum_{spiking p} w[p][q] ----
        __shared__ int   s_idx[PP];
        __shared__ int   s_wcnt[16];
        __shared__ int   s_woff[16];
        __shared__ int   s_cnt;
        __shared__ float s_part[4][128];

        const int b  = bid >> 4;                     // batch
        const int qt = bid & 15;                     // column tile
        const int tx = tid & 127;                    // column within tile
        const int ty = tid >> 7;                     // split-K slice (0..3)
        const int q  = qt * 128 + tx;

        // --- build this batch's spike index list via warp ballots ---
        const int wid  = tid >> 5;                   // 0..15
        const int lane = tid & 31;
        const float* row = pre_s + b * PP;
        const int e0 = 128 * wid + lane;
        const bool p0 = row[e0      ] > 0.0f;
        const bool p1 = row[e0 + 32 ] > 0.0f;
        const bool p2 = row[e0 + 64 ] > 0.0f;
        const bool p3 = row[e0 + 96 ] > 0.0f;
        const unsigned m0 = __ballot_sync(0xFFFFFFFFu, p0);
        const unsigned m1 = __ballot_sync(0xFFFFFFFFu, p1);
        const unsigned m2 = __ballot_sync(0xFFFFFFFFu, p2);
        const unsigned m3 = __ballot_sync(0xFFFFFFFFu, p3);
        if (lane == 0)
            s_wcnt[wid] = __popc(m0) + __popc(m1) + __popc(m2) + __popc(m3);
        __syncthreads();
        if (wid == 0 && lane < 16) {
            int c = s_wcnt[lane];
            int x = c;
#pragma unroll
            for (int off = 1; off < 16; off <<= 1) {
                int y = __shfl_up_sync(0x0000FFFFu, x, off, 16);
                if (lane >= off) x += y;
            }
            s_woff[lane] = x - c;                    // exclusive offsets
            if (lane == 15) s_cnt = x;
        }
        __syncthreads();
        {
            int off = s_woff[wid];
            const unsigned lt = (1u << lane) - 1u;
            if (p0) s_idx[off + __popc(m0 & lt)] = e0;
            off += __popc(m0);
            if (p1) s_idx[off + __popc(m1 & lt)] = e0 + 32;
            off += __popc(m1);
            if (p2) s_idx[off + __popc(m2 & lt)] = e0 + 64;
            off += __popc(m2);
            if (p3) s_idx[off + __popc(m3 & lt)] = e0 + 96;
        }
        __syncthreads();

        // --- split-K gather-sum, unroll 4 for MLP ---
        const int cnt   = s_cnt;
        const int per   = (cnt + 3) >> 2;
        const int start = ty * per;
        const int end   = min(start + per, cnt);

        float sum = 0.0f;
        int i = start;
        for (; i + 4 <= end; i += 4) {
            float a0 = w[s_idx[i + 0] * QQ + q];
            float a1 = w[s_idx[i + 1] * QQ + q];
            float a2 = w[s_idx[i + 2] * QQ + q];
            float a3 = w[s_idx[i + 3] * QQ + q];
            sum += (a0 + a1) + (a2 + a3);
        }
        for (; i < end; i++) sum += w[s_idx[i] * QQ + q];

        s_part[ty][tx] = sum;
        __syncthreads();

        if (ty == 0) {
            float t = ((s_part[0][tx] + s_part[1][tx]) +
                       (s_part[2][tx] + s_part[3][tx]));
            o_syn[b * QQ + q] = t;
        }

        // --- then one stream chunk (no sync needed; independent data) ---
        stream_chunk(bid, tid, w4, wc4, nw4);
    } else if (bid < 272) {
        // ---- Role C: trace updates (TAU_PLUS == TAU_MINUS == 0.02) ----
        const int g = bid - 256;
        const int i = g * 512 + tid;                 // < 8192 float4
        const float dt = dt_ptr ? dt_ptr[0] : 0.001f;
        const float decay = __expf(-dt / 0.02f);
        const float4* ps4 = (const float4*)pre_s;
        const float4* qs4 = (const float4*)post_s;
        const float4* pt4 = (const float4*)pre_tr;
        const float4* qt4 = (const float4*)post_tr;
        float4 a = pt4[i], sA = ps4[i];
        float4 bv = qt4[i], sB = qs4[i];
        float4 oa, ob;
        oa.x = fmaf(a.x, decay, sA.x); oa.y = fmaf(a.y, decay, sA.y);
        oa.z = fmaf(a.z, decay, sA.z); oa.w = fmaf(a.w, decay, sA.w);
        ob.x = fmaf(bv.x, decay, sB.x); ob.y = fmaf(bv.y, decay, sB.y);
        ob.z = fmaf(bv.z, decay, sB.z); ob.w = fmaf(bv.w, decay, sB.w);
        ((float4*)o_ptr)[i] = oa;
        ((float4*)o_qtr)[i] = ob;

        // --- then one stream chunk ---
        stream_chunk(256 + g, tid, w4, wc4, nw4);
    } else {
        // ---- Role A: stream only ----
        const int j = bid - 272;                     // 0..171
        if (j < 68) {
            stream_chunk(272 + 2 * j,     tid, w4, wc4, nw4);
            stream_chunk(272 + 2 * j + 1, tid, w4, wc4, nw4);
        } else {
            stream_chunk(408 + (j - 68), tid, w4, wc4, nw4);
        }
    }
}

// ---------------------------------------------------------------------------
// Launch
// Inputs (metadata order):
//  0 pre_spikes [16,2048]   1 post_spikes [16,2048]  2 weights [2048,2048]
//  3 pre_trace  [16,2048]   4 post_trace  [16,2048]
//  5 last_pre_spike (unused) 6 last_post_spike (unused)
//  7 current_time (unused)  8 dt (scalar)
// Output layout (tuple order, flattened):
//  [0, 32768)               synaptic_current
//  [32768, 4227072)         weight_changes
//  [4227072, 4259840)       pre_trace_new
//  [4259840, 4292608)       post_trace_new
//  [4292608, 8486912)       new_weights
// ---------------------------------------------------------------------------
extern "C" void kernel_launch(void* const* d_in, const int* in_sizes, int n_in,
                              void* d_out, int out_size) {
    const float* pre_s   = (const float*)d_in[0];
    const float* post_s  = (const float*)d_in[1];
    const float* weights = (const float*)d_in[2];
    const float* pre_tr  = (const float*)d_in[3];
    const float* post_tr = (const float*)d_in[4];
    const float* dt_ptr  = (n_in > 8) ? (const float*)d_in[8] : nullptr;

    float* out = (float*)d_out;
    float* o_syn = out;                    // 32768
    float* o_wc  = out + 32768;            // 4194304
    float* o_ptr = out + 4227072;          // 32768
    float* o_qtr = out + 4259840;          // 32768
    float* o_nw  = out + 4292608;          // 4194304

    k_fused<<<N_BLK, 512>>>(pre_s, post_s, weights, pre_tr, post_tr, dt_ptr,
                            o_syn, o_wc, o_ptr, o_qtr, o_nw);
    (void)in_sizes; (void)out_size;
}